// round 12
// baseline (speedup 1.0000x reference)
#include <cuda_runtime.h>

// Problem constants
#define A_ 3
#define T_ 32
#define C_ 4
#define R_ 8
#define K_ 1024
#define H_ 64
#define W_ 64
#define AC 12           // A_*C_
#define KT 32           // k's per block
#define NTHREADS 256
#define TCK 131072      // T_*C_*K_

typedef unsigned long long u64;

__device__ __forceinline__ u64 pack2(float lo, float hi) {
    u64 r; asm("mov.b64 %0, {%1, %2};" : "=l"(r) : "f"(lo), "f"(hi)); return r;
}
__device__ __forceinline__ void unpack2(u64 v, float &lo, float &hi) {
    asm("mov.b64 {%0, %1}, %2;" : "=f"(lo), "=f"(hi) : "l"(v));
}
__device__ __forceinline__ void ffma2(u64 &acc, u64 a, u64 b) {
    asm("fma.rn.f32x2 %0, %1, %2, %0;" : "+l"(acc) : "l"(a), "l"(b));
}

union F4 { float4 v; u64 p[2]; };

// cross-kernel partials: [h-half][r][ac][k], each cell written by exactly one block
__device__ float g_ypart[2][R_][AC][K_];

// kernel-1 smem layout (dynamic, 104KB -> 2 CTAs/SM):
//   [0, 98304)       : sym[12 ac][32 hl][64]: [0:32)=se(m), [32:64)=so(m)
//                      (so(0) slot holds s(w=0) for the m=32 correction)
//   [98304, 102400)  : cpr[16 mp][32 k] float2 paired cos
//   [102400, 106496) : snr[16 mp][32 k] float2 paired -sin
// after main loop (reuse): [0, 12288) yp[8 warp][12 ac][32 k] float
#define SMEM_CPR_OFF   98304
#define SMEM_SNR_OFF   102400
#define SMEM_BYTES     106496

extern __shared__ char smem_raw[];

__global__ __launch_bounds__(NTHREADS, 2)
void nufft_stage1(const float* __restrict__ x,
                  const float* __restrict__ cand0,   // trj or mps
                  const float* __restrict__ cand1)   // the other one
{
    float* s_s = (float*)smem_raw;
    float* cpf = (float*)(smem_raw + SMEM_CPR_OFF);
    float* snf = (float*)(smem_raw + SMEM_SNR_OFF);

    const int tid  = threadIdx.x;
    const int r    = blockIdx.x >> 6;            // 8 trajectories
    const int kt   = (blockIdx.x >> 1) & 31;     // 32 k-tiles
    const int hh2  = blockIdx.x & 1;             // h-half
    const int k0   = kt * KT;
    const int h0   = hh2 * 32;
    const int lane = tid & 31;                   // k within tile
    const int wid  = tid >> 5;                   // warp: 4 h's each

    // ---- disambiguate trj vs mps: trj bounded by pi, mps ~ N(0,1) ----
    int big = 0;
    for (int i = tid; i < 16384 / 4; i += NTHREADS) {
        float4 v = ((const float4*)cand0)[i];
        big |= (fabsf(v.x) > 3.1416f) | (fabsf(v.y) > 3.1416f) |
               (fabsf(v.z) > 3.1416f) | (fabsf(v.w) > 3.1416f);
    }
    const int c0_is_mps = __syncthreads_or(big);
    const float* trj = c0_is_mps ? cand1 : cand0;
    const float* mps = c0_is_mps ? cand0 : cand1;

    // ---- build symmetrized se/so for this block's 32 h-rows ----
    for (int idx = tid; idx < AC * 32 * 8; idx += NTHREADS) {
        int j  = idx & 7;
        int hl = (idx >> 3) & 31;
        int ac = idx >> 8;
        int a = ac >> 2, c = ac & 3;
        int h = h0 + hl;
        const float* xr = x   + (a * H_ + h) * W_;
        const float* mr = mps + (c * H_ + h) * W_;

        float4 xp = *(const float4*)(xr + 32 + 4 * j);
        float4 mp = *(const float4*)(mr + 32 + 4 * j);
        float sp0 = xp.x * mp.x, sp1 = xp.y * mp.y;
        float sp2 = xp.z * mp.z, sp3 = xp.w * mp.w;

        float sm0 = xr[32 - 4 * j - 0] * mr[32 - 4 * j - 0];
        float sm1 = xr[32 - 4 * j - 1] * mr[32 - 4 * j - 1];
        float sm2 = xr[32 - 4 * j - 2] * mr[32 - 4 * j - 2];
        float sm3 = xr[32 - 4 * j - 3] * mr[32 - 4 * j - 3];

        float4 se4 = make_float4(sp0 + sm0, sp1 + sm1, sp2 + sm2, sp3 + sm3);
        float4 so4 = make_float4(sp0 - sm0, sp1 - sm1, sp2 - sm2, sp3 - sm3);
        if (j == 0) {
            se4.x = sp0;                 // center m=0: just s(32)
            so4.x = xr[0] * mr[0];       // stash s(w=0) for the m=32 correction
        }
        float* row = s_s + (ac * 32 + hl) * 64;
        *(float4*)(row + 4 * j)      = se4;
        *(float4*)(row + 32 + 4 * j) = so4;
    }

    // ---- build paired cos / (-sin) planes for m in [0,32) ----
    for (int i = tid; i < 32 * KT; i += NTHREADS) {
        int m = i >> 5, kk = i & 31;
        float wxk = trj[(r * 2 + 1) * K_ + k0 + kk];
        float sn, cs; sincosf((float)m * wxk, &sn, &cs);
        int off = (m >> 1) * 64 + kk * 2 + (m & 1);
        cpf[off] = cs;
        snf[off] = -sn;
    }
    __syncthreads();

    const float wy = trj[(r * 2 + 0) * K_ + k0 + lane];
    const float wx = trj[(r * 2 + 1) * K_ + k0 + lane];
    float s32v, c32v; sincosf(32.0f * wx, &s32v, &c32v);

    const u64* cp64 = (const u64*)cpf;
    const u64* sn64 = (const u64*)snf;

    // persistent accumulators: Re(y) as (even-m, odd-m) pairs
    u64 acc_re2[AC];
    #pragma unroll
    for (int ac = 0; ac < AC; ac++) acc_re2[ac] = 0ull;

    // ==== main loop: 4 ac-triples x this warp's 4 h's ====
    #pragma unroll
    for (int t4 = 0; t4 < 4; t4++) {
        const int ac0 = t4 * 3;
        #pragma unroll
        for (int hl4 = 0; hl4 < 4; hl4++) {
            const int hl = wid * 4 + hl4;
            const int h  = h0 + hl;

            u64 ire[3], iim[3];
            #pragma unroll
            for (int i = 0; i < 3; i++) { ire[i] = 0ull; iim[i] = 0ull; }

            #pragma unroll
            for (int j = 0; j < 8; j++) {          // m4 = {4j..4j+3}
                u64 c0 = cp64[(2 * j + 0) * 32 + lane];
                u64 c1 = cp64[(2 * j + 1) * 32 + lane];
                u64 n0 = sn64[(2 * j + 0) * 32 + lane];
                u64 n1 = sn64[(2 * j + 1) * 32 + lane];

                #pragma unroll
                for (int i = 0; i < 3; i++) {
                    const float* row = s_s + ((ac0 + i) * 32 + hl) * 64;
                    F4 se; se.v = *(const float4*)(row + 4 * j);        // broadcast
                    F4 so; so.v = *(const float4*)(row + 32 + 4 * j);   // broadcast
                    ffma2(ire[i], c0, se.p[0]);
                    ffma2(ire[i], c1, se.p[1]);
                    ffma2(iim[i], n0, so.p[0]);
                    ffma2(iim[i], n1, so.p[1]);
                }
            }

            // fold: Re(acc) += cy*ire - sy*iim + s0*(cy*c32 - sy*s32)
            float ang = -wy * (float)(h - H_ / 2);
            float sy, cy; sincosf(ang, &sy, &cy);
            u64 cy2  = pack2(cy, cy);
            u64 sy2n = pack2(-sy, -sy);
            u64 cc2  = pack2(cy * c32v - sy * s32v, 0.0f);
            #pragma unroll
            for (int i = 0; i < 3; i++) {
                float s0 = s_s[((ac0 + i) * 32 + hl) * 64 + 32];  // so-slot 0 = s(w=0)
                ffma2(acc_re2[ac0 + i], cy2, ire[i]);
                ffma2(acc_re2[ac0 + i], sy2n, iim[i]);
                ffma2(acc_re2[ac0 + i], cc2, pack2(s0, 0.0f));
            }
        }
    }

    // ---- reduce 8 warps' partials, write to global y_part ----
    __syncthreads();                              // all reads of s_s/planes done
    float* yp = (float*)smem_raw;                 // [8][12][32]
    #pragma unroll
    for (int ac = 0; ac < AC; ac++) {
        float lo, hi; unpack2(acc_re2[ac], lo, hi);
        yp[(wid * AC + ac) * KT + lane] = lo + hi;
    }
    __syncthreads();

    for (int i = tid; i < AC * KT; i += NTHREADS) {
        int ac = i >> 5, kk = i & 31;
        float re = 0.f;
        #pragma unroll
        for (int p = 0; p < 8; p++) re += yp[p * (AC * KT) + i];
        g_ypart[hh2][r][ac][k0 + kk] = re;
    }
}

// ==== stage 2: sum h-halves, phi-mix, dcf, subsample, write ====
__global__ __launch_bounds__(NTHREADS, 4)
void nufft_stage2(const float* __restrict__ phi,
                  const float* __restrict__ dcf,
                  const int* __restrict__ sidx32,
                  float* __restrict__ outf,
                  int mode)
{
    int idx = blockIdx.x * NTHREADS + threadIdx.x;   // [0, T*C*K)
    int t = idx >> 12;
    int c = (idx >> 10) & 3;
    int k = idx & 1023;

    // detect subsamp_idx width: int64 (odd words zero) vs int32
    bool is64 = true;
    #pragma unroll
    for (int tt = 0; tt < T_; tt++)
        if (sidx32[2 * tt + 1] != 0) is64 = false;
    int r = is64 ? sidx32[2 * t] : sidx32[t];

    float re = 0.f;
    #pragma unroll
    for (int a = 0; a < A_; a++) {
        float y = g_ypart[0][r][a * C_ + c][k] + g_ypart[1][r][a * C_ + c][k];
        re = fmaf(phi[a * T_ + t], y, re);
    }
    re *= dcf[r * K_ + k];

    if (mode == 0) {
        outf[idx] = re;                                  // real-only float32 (live path)
    } else {
        ((float2*)outf)[idx] = make_float2(re, 0.f);     // defensive fallback
    }
}

extern "C" void kernel_launch(void* const* d_in, const int* in_sizes, int n_in,
                              void* d_out, int out_size) {
    // Identify inputs by element count (robust to ordering):
    //   x: 12288, phi: 96, sqrt_dcf: 8192, subsamp_idx: 32,
    //   trj & mps: both 16384 (disambiguated in-kernel by value range)
    const float *x = 0, *phi = 0, *dcf = 0, *c0 = 0, *c1 = 0;
    const int *sidx = 0;
    for (int i = 0; i < n_in; i++) {
        switch (in_sizes[i]) {
            case 12288: x    = (const float*)d_in[i]; break;
            case 96:    phi  = (const float*)d_in[i]; break;
            case 8192:  dcf  = (const float*)d_in[i]; break;
            case 32:    sidx = (const int*)d_in[i];   break;
            case 16384: if (!c0) c0 = (const float*)d_in[i];
                        else     c1 = (const float*)d_in[i];
                        break;
            default: break;
        }
    }
    if (!x || !phi || !dcf || !sidx || !c0 || !c1) {
        x    = (const float*)d_in[0];
        c0   = (const float*)d_in[1];
        phi  = (const float*)d_in[2];
        c1   = (const float*)d_in[3];
        dcf  = (const float*)d_in[4];
        sidx = (const int*)d_in[5];
    }

    int mode = (out_size == TCK) ? 0 : 2;

    cudaFuncSetAttribute(nufft_stage1,
                         cudaFuncAttributeMaxDynamicSharedMemorySize, SMEM_BYTES);
    nufft_stage1<<<R_ * 32 * 2, NTHREADS, SMEM_BYTES>>>(x, c0, c1);
    nufft_stage2<<<TCK / NTHREADS, NTHREADS>>>(phi, dcf, sidx, (float*)d_out, mode);
}

// round 13
// speedup vs baseline: 1.0733x; 1.0733x over previous
#include <cuda_runtime.h>

// Problem constants
#define A_ 3
#define T_ 32
#define C_ 4
#define R_ 8
#define K_ 1024
#define H_ 64
#define W_ 64
#define AC 12           // A_*C_
#define KT 64           // k's per block (thread covers k and k+32)
#define NTHREADS 256
#define TCK 131072      // T_*C_*K_

typedef unsigned long long u64;

__device__ __forceinline__ u64 pack2(float lo, float hi) {
    u64 r; asm("mov.b64 %0, {%1, %2};" : "=l"(r) : "f"(lo), "f"(hi)); return r;
}
__device__ __forceinline__ void unpack2(u64 v, float &lo, float &hi) {
    asm("mov.b64 {%0, %1}, %2;" : "=f"(lo), "=f"(hi) : "l"(v));
}
__device__ __forceinline__ void ffma2(u64 &acc, u64 a, u64 b) {
    asm("fma.rn.f32x2 %0, %1, %2, %0;" : "+l"(acc) : "l"(a), "l"(b));
}

union F4 { float4 v; u64 p[2]; };

// cross-kernel partials: [h-half][r][ac][k], each cell written by exactly one block
__device__ float g_ypart[2][R_][AC][K_];

// stage-1 smem (213KB -> 1 CTA/SM):
//   [0, 196608)      : symdup[12 ac][32 hl][64 slots] float2 (value duplicated):
//                      slots [0:32) = se(m) dup, [32:64) = so(m) dup
//                      (se(0)=s(32); so(0) slot carries s(w=0) — its table sin(0)
//                      weight is 0; used by the m=32 correction)
//   [196608, 204800) : tc2[32 m][32 lane] float2 = ( cos(m*wx_ka),  cos(m*wx_kb))
//   [204800, 212992) : ts2[32 m][32 lane] float2 = (-sin(m*wx_ka), -sin(m*wx_kb))
// after main loop (reuse): [0, 24576) yp[8 warp][12 ac][64 k] float
#define SMEM_TC_OFF   196608
#define SMEM_TS_OFF   204800
#define SMEM_BYTES    212992

extern __shared__ char smem_raw[];

__global__ __launch_bounds__(NTHREADS, 1)
void nufft_stage1(const float* __restrict__ x,
                  const float* __restrict__ cand0,   // trj or mps
                  const float* __restrict__ cand1)   // the other one
{
    float* symf = (float*)smem_raw;
    float* tcf  = (float*)(smem_raw + SMEM_TC_OFF);
    float* tsf  = (float*)(smem_raw + SMEM_TS_OFF);

    const int tid  = threadIdx.x;
    const int r    = blockIdx.x >> 5;            // 8 trajectories
    const int kt   = (blockIdx.x >> 1) & 15;     // 16 k-tiles of 64
    const int hh   = blockIdx.x & 1;             // h-half
    const int k0   = kt * KT;
    const int h0   = hh * 32;
    const int lane = tid & 31;
    const int wid  = tid >> 5;                   // warp: 4 h's each

    // ---- disambiguate trj vs mps: trj bounded by pi, mps ~ N(0,1) ----
    int big = 0;
    for (int i = tid; i < 16384 / 4; i += NTHREADS) {
        float4 v = ((const float4*)cand0)[i];
        big |= (fabsf(v.x) > 3.1416f) | (fabsf(v.y) > 3.1416f) |
               (fabsf(v.z) > 3.1416f) | (fabsf(v.w) > 3.1416f);
    }
    const int c0_is_mps = __syncthreads_or(big);
    const float* trj = c0_is_mps ? cand1 : cand0;
    const float* mps = c0_is_mps ? cand0 : cand1;

    // ---- build DUPLICATED symmetrized se/so for this block's 32 h-rows ----
    for (int idx = tid; idx < AC * 32 * 8; idx += NTHREADS) {
        int j  = idx & 7;
        int hl = (idx >> 3) & 31;
        int ac = idx >> 8;
        int a = ac >> 2, c = ac & 3;
        int h = h0 + hl;
        const float* xr = x   + (a * H_ + h) * W_;
        const float* mr = mps + (c * H_ + h) * W_;

        float4 xp = *(const float4*)(xr + 32 + 4 * j);
        float4 mp = *(const float4*)(mr + 32 + 4 * j);
        float sp0 = xp.x * mp.x, sp1 = xp.y * mp.y;
        float sp2 = xp.z * mp.z, sp3 = xp.w * mp.w;

        float sm0 = xr[32 - 4 * j - 0] * mr[32 - 4 * j - 0];
        float sm1 = xr[32 - 4 * j - 1] * mr[32 - 4 * j - 1];
        float sm2 = xr[32 - 4 * j - 2] * mr[32 - 4 * j - 2];
        float sm3 = xr[32 - 4 * j - 3] * mr[32 - 4 * j - 3];

        float se0 = sp0 + sm0, se1 = sp1 + sm1, se2 = sp2 + sm2, se3 = sp3 + sm3;
        float so0 = sp0 - sm0, so1 = sp1 - sm1, so2 = sp2 - sm2, so3 = sp3 - sm3;
        if (j == 0) {
            se0 = sp0;               // center m=0: just s(32)
            so0 = xr[0] * mr[0];     // stash s(w=0) for the m=32 correction
        }
        // duplicated stores: slot m is float2 (v, v)
        float* row = symf + (ac * 32 + hl) * 128;       // 64 slots * 2 floats
        *(float4*)(row + 8 * j)      = make_float4(se0, se0, se1, se1);
        *(float4*)(row + 8 * j + 4)  = make_float4(se2, se2, se3, se3);
        *(float4*)(row + 64 + 8 * j)     = make_float4(so0, so0, so1, so1);
        *(float4*)(row + 64 + 8 * j + 4) = make_float4(so2, so2, so3, so3);
    }

    // ---- build k-paired trig tables for m in [0,32) ----
    for (int i = tid; i < 32 * KT; i += NTHREADS) {
        int m = i >> 6, k64 = i & 63;
        float wxk = trj[(r * 2 + 1) * K_ + k0 + k64];
        float sn, cs; sincosf((float)m * wxk, &sn, &cs);
        int col = k64 & 31, half = k64 >> 5;
        tcf[(m * 32 + col) * 2 + half] = cs;
        tsf[(m * 32 + col) * 2 + half] = -sn;
    }
    __syncthreads();

    // per-thread k pair: k_a = k0+lane, k_b = k0+lane+32
    const float wy_a = trj[(r * 2 + 0) * K_ + k0 + lane];
    const float wy_b = trj[(r * 2 + 0) * K_ + k0 + lane + 32];
    const float wx_a = trj[(r * 2 + 1) * K_ + k0 + lane];
    const float wx_b = trj[(r * 2 + 1) * K_ + k0 + lane + 32];
    float s32a, c32a; sincosf(32.0f * wx_a, &s32a, &c32a);
    float s32b, c32b; sincosf(32.0f * wx_b, &s32b, &c32b);

    const u64* tc64 = (const u64*)tcf;   // [m*32 + lane]
    const u64* ts64 = (const u64*)tsf;

    u64 acc[AC];                          // lanes = (k_a, k_b), real part
    #pragma unroll
    for (int i = 0; i < AC; i++) acc[i] = 0ull;

    // ==== main loop: this warp's 4 h-rows, all 12 acs in flight ====
    #pragma unroll
    for (int hl4 = 0; hl4 < 4; hl4++) {
        const int hl = wid * 4 + hl4;
        const float hm = (float)(h0 + hl - 32);

        float sya, cya; sincosf(-wy_a * hm, &sya, &cya);
        float syb, cyb; sincosf(-wy_b * hm, &syb, &cyb);
        u64 cy2  = pack2(cya, cyb);
        u64 sy2n = pack2(-sya, -syb);
        u64 cc2  = pack2(cya * c32a - sya * s32a, cyb * c32b - syb * s32b);

        u64 ire[AC], iim[AC];
        #pragma unroll
        for (int i = 0; i < AC; i++) { ire[i] = 0ull; iim[i] = 0ull; }

        #pragma unroll
        for (int j = 0; j < 8; j++) {            // m4 = {4j..4j+3}
            u64 t0 = tc64[(4 * j + 0) * 32 + lane];
            u64 t1 = tc64[(4 * j + 1) * 32 + lane];
            u64 t2 = tc64[(4 * j + 2) * 32 + lane];
            u64 t3 = tc64[(4 * j + 3) * 32 + lane];
            u64 u0 = ts64[(4 * j + 0) * 32 + lane];
            u64 u1 = ts64[(4 * j + 1) * 32 + lane];
            u64 u2 = ts64[(4 * j + 2) * 32 + lane];
            u64 u3 = ts64[(4 * j + 3) * 32 + lane];

            #pragma unroll
            for (int i = 0; i < AC; i++) {
                const float* row = symf + (i * 32 + hl) * 128;
                F4 se01; se01.v = *(const float4*)(row + 8 * j);          // broadcast
                F4 se23; se23.v = *(const float4*)(row + 8 * j + 4);
                F4 so01; so01.v = *(const float4*)(row + 64 + 8 * j);
                F4 so23; so23.v = *(const float4*)(row + 64 + 8 * j + 4);
                ffma2(ire[i], t0, se01.p[0]);
                ffma2(ire[i], t1, se01.p[1]);
                ffma2(ire[i], t2, se23.p[0]);
                ffma2(ire[i], t3, se23.p[1]);
                ffma2(iim[i], u0, so01.p[0]);
                ffma2(iim[i], u1, so01.p[1]);
                ffma2(iim[i], u2, so23.p[0]);
                ffma2(iim[i], u3, so23.p[1]);
            }
        }

        // fold: Re(acc) += cy*ire - sy*iim + s0*(cy*c32 - sy*s32)   per lane
        #pragma unroll
        for (int i = 0; i < AC; i++) {
            const float* row = symf + (i * 32 + hl) * 128;
            u64 s0d = *(const u64*)(row + 64);    // so slot 0 dup = (s(w=0), s(w=0))
            ffma2(acc[i], cy2, ire[i]);
            ffma2(acc[i], sy2n, iim[i]);
            ffma2(acc[i], cc2, s0d);
        }
    }

    // ---- reduce 8 warps' partials, write global y_part ----
    __syncthreads();                              // all reads of symdup/tables done
    float* yp = (float*)smem_raw;                 // [8 warp][12 ac][64 k]
    #pragma unroll
    for (int i = 0; i < AC; i++) {
        float va, vb; unpack2(acc[i], va, vb);
        yp[(wid * AC + i) * KT + lane]      = va;
        yp[(wid * AC + i) * KT + lane + 32] = vb;
    }
    __syncthreads();

    for (int i = tid; i < AC * KT; i += NTHREADS) {
        int ac = i >> 6, kk = i & 63;
        float re = 0.f;
        #pragma unroll
        for (int p = 0; p < 8; p++) re += yp[p * (AC * KT) + i];
        g_ypart[hh][r][ac][k0 + kk] = re;
    }
}

// ==== stage 2: sum h-halves, phi-mix, dcf, subsample, write ====
__global__ __launch_bounds__(NTHREADS, 4)
void nufft_stage2(const float* __restrict__ phi,
                  const float* __restrict__ dcf,
                  const int* __restrict__ sidx32,
                  float* __restrict__ outf,
                  int mode)
{
    int idx = blockIdx.x * NTHREADS + threadIdx.x;   // [0, T*C*K)
    int t = idx >> 12;
    int c = (idx >> 10) & 3;
    int k = idx & 1023;

    // detect subsamp_idx width: int64 (odd words zero) vs int32
    bool is64 = true;
    #pragma unroll
    for (int tt = 0; tt < T_; tt++)
        if (sidx32[2 * tt + 1] != 0) is64 = false;
    int r = is64 ? sidx32[2 * t] : sidx32[t];

    float re = 0.f;
    #pragma unroll
    for (int a = 0; a < A_; a++) {
        float y = g_ypart[0][r][a * C_ + c][k] + g_ypart[1][r][a * C_ + c][k];
        re = fmaf(phi[a * T_ + t], y, re);
    }
    re *= dcf[r * K_ + k];

    if (mode == 0) {
        outf[idx] = re;                                  // real-only float32 (live path)
    } else {
        ((float2*)outf)[idx] = make_float2(re, 0.f);     // defensive fallback
    }
}

extern "C" void kernel_launch(void* const* d_in, const int* in_sizes, int n_in,
                              void* d_out, int out_size) {
    // Identify inputs by element count (robust to ordering):
    //   x: 12288, phi: 96, sqrt_dcf: 8192, subsamp_idx: 32,
    //   trj & mps: both 16384 (disambiguated in-kernel by value range)
    const float *x = 0, *phi = 0, *dcf = 0, *c0 = 0, *c1 = 0;
    const int *sidx = 0;
    for (int i = 0; i < n_in; i++) {
        switch (in_sizes[i]) {
            case 12288: x    = (const float*)d_in[i]; break;
            case 96:    phi  = (const float*)d_in[i]; break;
            case 8192:  dcf  = (const float*)d_in[i]; break;
            case 32:    sidx = (const int*)d_in[i];   break;
            case 16384: if (!c0) c0 = (const float*)d_in[i];
                        else     c1 = (const float*)d_in[i];
                        break;
            default: break;
        }
    }
    if (!x || !phi || !dcf || !sidx || !c0 || !c1) {
        x    = (const float*)d_in[0];
        c0   = (const float*)d_in[1];
        phi  = (const float*)d_in[2];
        c1   = (const float*)d_in[3];
        dcf  = (const float*)d_in[4];
        sidx = (const int*)d_in[5];
    }

    int mode = (out_size == TCK) ? 0 : 2;

    cudaFuncSetAttribute(nufft_stage1,
                         cudaFuncAttributeMaxDynamicSharedMemorySize, SMEM_BYTES);
    nufft_stage1<<<R_ * 16 * 2, NTHREADS, SMEM_BYTES>>>(x, c0, c1);
    nufft_stage2<<<TCK / NTHREADS, NTHREADS>>>(phi, dcf, sidx, (float*)d_out, mode);
}